// round 12
// baseline (speedup 1.0000x reference)
#include <cuda_runtime.h>
#include <cuda_fp16.h>
#include <cuda_bf16.h>
#include <cstdint>
#include <cstddef>

// Problem constants
#define BATCH 8
#define SEQ   512
#define NTOK  4096      // BATCH*SEQ
#define EMB   1024
#define E3    3072
#define NHEAD 16
#define HDIM  64
#define HID   4096
#define ODIM  128
#define NLAYER 8

// ---------------------------------------------------------------------------
// Scratch (device globals; allocation is forbidden)
// ---------------------------------------------------------------------------
__device__ float g_z   [(size_t)NTOK * EMB];   // fp32 residual stream
__device__ float g_qkv [(size_t)NTOK * E3];
__device__ float g_attn[(size_t)NTOK * EMB];
__device__ float g_tmp [(size_t)NTOK * EMB];
__device__ float g_hid [(size_t)NTOK * HID];
__device__ float g_M   [ODIM * ODIM];
__device__ float g_aug [ODIM * 2 * ODIM];
__device__ float g_P   [ODIM * EMB];

// int8 limb buffers
#define WTOT ((size_t)NLAYER*E3*EMB + (size_t)NLAYER*EMB*EMB + \
              2*(size_t)NLAYER*HID*EMB + (size_t)ODIM*EMB)
#define WROWS (NLAYER*(E3 + EMB + HID + EMB) + ODIM)   // 73856
__device__ int8_t g_wq1[WTOT];
__device__ int8_t g_wq2[WTOT];
__device__ float  g_ws [WROWS];
__device__ int8_t g_zq1[(size_t)NTOK * EMB];
__device__ int8_t g_zq2[(size_t)NTOK * EMB];
__device__ float  g_zs [NTOK];
__device__ int8_t g_aq1[(size_t)NTOK * EMB];
__device__ int8_t g_aq2[(size_t)NTOK * EMB];
__device__ float  g_as [NTOK];
__device__ int8_t g_hq1[(size_t)NTOK * HID];
__device__ int8_t g_hq2[(size_t)NTOK * HID];
__device__ float  g_hs [NTOK];

#define INV254 (1.0f / 254.0f)
#define INVQ   (1.0f / 16129.0f)   // 1/(127*127)

// ---------------------------------------------------------------------------
// helpers
// ---------------------------------------------------------------------------
__device__ __forceinline__ void ldmatrix4(uint32_t addr, uint32_t& r0, uint32_t& r1,
                                          uint32_t& r2, uint32_t& r3)
{
    asm volatile("ldmatrix.sync.aligned.m8n8.x4.shared.b16 {%0,%1,%2,%3}, [%4];"
                 : "=r"(r0), "=r"(r1), "=r"(r2), "=r"(r3) : "r"(addr));
}

// s8 IMMA, K=32 per instruction; fragment byte-layout identical to f16 k16
__device__ __forceinline__ void mma_s8(int* c, uint32_t a0, uint32_t a1,
                                       uint32_t a2, uint32_t a3,
                                       uint32_t b0, uint32_t b1)
{
    asm volatile("mma.sync.aligned.m16n8k32.row.col.s32.s8.s8.s32 "
                 "{%0,%1,%2,%3},{%4,%5,%6,%7},{%8,%9},{%0,%1,%2,%3};"
                 : "+r"(c[0]), "+r"(c[1]), "+r"(c[2]), "+r"(c[3])
                 : "r"(a0), "r"(a1), "r"(a2), "r"(a3), "r"(b0), "r"(b1));
}

__device__ __forceinline__ void cpasync16(uint32_t s, const void* g)
{
    asm volatile("cp.async.cg.shared.global [%0], [%1], 16;" :: "r"(s), "l"(g));
}

// ===========================================================================
// Row quantization: x = s/127 * (q1 + q2/254), s = rowmax
// one block per row
// ===========================================================================
__global__ void __launch_bounds__(256) quant_kernel(const float* __restrict__ src,
                                                    int8_t* __restrict__ q1,
                                                    int8_t* __restrict__ q2,
                                                    float* __restrict__ s, int K)
{
    __shared__ float sbuf[8];
    const size_t row = blockIdx.x;
    const float* p = src + row * (size_t)K;
    float m = 0.f;
    for (int i = threadIdx.x; i < K; i += 256) m = fmaxf(m, fabsf(p[i]));
#pragma unroll
    for (int o = 16; o; o >>= 1) m = fmaxf(m, __shfl_xor_sync(0xffffffffu, m, o));
    if ((threadIdx.x & 31) == 0) sbuf[threadIdx.x >> 5] = m;
    __syncthreads();
    float mx = sbuf[0];
#pragma unroll
    for (int i = 1; i < 8; i++) mx = fmaxf(mx, sbuf[i]);
    mx = fmaxf(mx, 1e-30f);
    if (threadIdx.x == 0) s[row] = mx;
    const float inv = 127.f / mx;
    for (int i = threadIdx.x; i < K; i += 256) {
        float x = p[i] * inv;
        float r1 = rintf(x);
        float r2 = rintf((x - r1) * 254.f);
        q1[row * (size_t)K + i] = (int8_t)r1;
        q2[row * (size_t)K + i] = (int8_t)r2;
    }
}

// ===========================================================================
// INT8 tensor-core GEMM: C[M,N] = A[M,K]*B[N,K]^T, 2-limb split, 3 IMMA terms.
// 128x128 tile, K-chunk 64 (bytes), 2-stage cp.async, 256 threads.
// op: 0=none, 1=bias, 2=bias+relu   (fp32 output always)
// ===========================================================================
#define RW  20                  // words per smem row: 16 data (64 int8) + 4 pad
#define PLANE  (128 * RW)       // 2560 words
#define STAGEW (4 * PLANE)      // 10240 words (40 KB)
#define TC_SMEM (2 * STAGEW * 4)

__global__ void __launch_bounds__(256, 1) gemm_i8_kernel(
    const int8_t* __restrict__ A1, const int8_t* __restrict__ A2,
    const float* __restrict__ sa,
    const int8_t* __restrict__ B1, const int8_t* __restrict__ B2,
    const float* __restrict__ sb,
    const float* __restrict__ bias, float* __restrict__ C,
    int M, int N, int K, int op)
{
    extern __shared__ uint32_t sm[];
    const uint32_t sbase = (uint32_t)__cvta_generic_to_shared(sm);

    const int tid = threadIdx.x;
    const int lane = tid & 31;
    const int wid = tid >> 5;
    const int wm = wid >> 2;      // 0..1  (64-row slab)
    const int wn = wid & 3;       // 0..3  (32-col slab)
    const int bm = blockIdx.y * 128;
    const int bn = blockIdx.x * 128;

    int accM[4][4][4];            // q1a*q1b
    int accC[4][4][4];            // q1a*q2b + q2a*q1b (shared accumulator)
#pragma unroll
    for (int i = 0; i < 4; i++)
#pragma unroll
        for (int j = 0; j < 4; j++)
#pragma unroll
            for (int r = 0; r < 4; r++) { accM[i][j][r] = 0; accC[i][j][r] = 0; }

    // cp.async mapping: 4 planes x 128 rows x 4 chunks(16B) = 2048 chunks, 8/thread
    const int8_t* gsrc[8];
    uint32_t soff[8];
#pragma unroll
    for (int i = 0; i < 8; i++) {
        int idx = tid + i * 256;
        int pl = idx >> 9;
        int r  = (idx >> 2) & 127;
        int c  = idx & 3;
        const int8_t* base =
            (pl == 0) ? A1 + (size_t)(bm + r) * K :
            (pl == 1) ? A2 + (size_t)(bm + r) * K :
            (pl == 2) ? B1 + (size_t)(bn + r) * K :
                        B2 + (size_t)(bn + r) * K;
        gsrc[i] = base + c * 16;
        soff[i] = 4u * (uint32_t)(pl * PLANE + r * RW + c * 4);
    }

    const int T = K / 64;
#pragma unroll
    for (int i = 0; i < 8; i++) cpasync16(sbase + soff[i], gsrc[i]);
    asm volatile("cp.async.commit_group;");

    // ldmatrix lane addressing (verified layout; s8 k32 == f16 k16 byte layout)
    const int arow = wm * 64 + (lane & 7) + ((lane & 8) ? 8 : 0);
    const int akw0 = (lane & 16) ? 4 : 0;
    const int brow = wn * 32 + (lane & 7) + ((lane & 16) ? 8 : 0);
    const int bkw0 = (lane & 8) ? 4 : 0;

    for (int t = 0; t < T; t++) {
        if (t + 1 < T) {
            const uint32_t sb2 = sbase + (uint32_t)(((t + 1) & 1) * STAGEW) * 4u;
            const int k0 = (t + 1) * 64;
#pragma unroll
            for (int i = 0; i < 8; i++) cpasync16(sb2 + soff[i], gsrc[i] + k0);
            asm volatile("cp.async.commit_group;");
            asm volatile("cp.async.wait_group 1;");
        } else {
            asm volatile("cp.async.wait_group 0;");
        }
        __syncthreads();

        const uint32_t bufb = sbase + (uint32_t)((t & 1) * STAGEW) * 4u;
#pragma unroll
        for (int ks = 0; ks < 2; ks++) {
            const int akw = ks * 8 + akw0;
            const int bkw = ks * 8 + bkw0;
            uint32_t a1[4][4], a2[4][4], b1[4][2], b2[4][2];
#pragma unroll
            for (int mt = 0; mt < 4; mt++) {
                ldmatrix4(bufb + 4u * (0 * PLANE + (arow + mt * 16) * RW + akw),
                          a1[mt][0], a1[mt][1], a1[mt][2], a1[mt][3]);
                ldmatrix4(bufb + 4u * (1 * PLANE + (arow + mt * 16) * RW + akw),
                          a2[mt][0], a2[mt][1], a2[mt][2], a2[mt][3]);
            }
#pragma unroll
            for (int np = 0; np < 2; np++) {
                uint32_t r0, r1, r2, r3;
                ldmatrix4(bufb + 4u * (2 * PLANE + (brow + np * 16) * RW + bkw),
                          r0, r1, r2, r3);
                b1[2 * np][0] = r0; b1[2 * np][1] = r1;
                b1[2 * np + 1][0] = r2; b1[2 * np + 1][1] = r3;
                ldmatrix4(bufb + 4u * (3 * PLANE + (brow + np * 16) * RW + bkw),
                          r0, r1, r2, r3);
                b2[2 * np][0] = r0; b2[2 * np][1] = r1;
                b2[2 * np + 1][0] = r2; b2[2 * np + 1][1] = r3;
            }
            // term-major: independent accumulators within each pass
#pragma unroll
            for (int mt = 0; mt < 4; mt++)
#pragma unroll
                for (int nt = 0; nt < 4; nt++)
                    mma_s8(accM[mt][nt], a1[mt][0], a1[mt][1], a1[mt][2], a1[mt][3],
                           b1[nt][0], b1[nt][1]);
#pragma unroll
            for (int mt = 0; mt < 4; mt++)
#pragma unroll
                for (int nt = 0; nt < 4; nt++)
                    mma_s8(accC[mt][nt], a1[mt][0], a1[mt][1], a1[mt][2], a1[mt][3],
                           b2[nt][0], b2[nt][1]);
#pragma unroll
            for (int mt = 0; mt < 4; mt++)
#pragma unroll
                for (int nt = 0; nt < 4; nt++)
                    mma_s8(accC[mt][nt], a2[mt][0], a2[mt][1], a2[mt][2], a2[mt][3],
                           b1[nt][0], b1[nt][1]);
        }
        __syncthreads();
    }

    // ---- epilogue: dequantize, bias/relu, fp32 store ----
#pragma unroll
    for (int mt = 0; mt < 4; mt++) {
        const int row = bm + wm * 64 + mt * 16 + (lane >> 2);
        const float sA0 = sa[row] * INVQ;
        const float sA8 = sa[row + 8] * INVQ;
#pragma unroll
        for (int nt = 0; nt < 4; nt++) {
            const int col = bn + wn * 32 + nt * 8 + 2 * (lane & 3);
            const float sB0 = sb[col], sB1 = sb[col + 1];
            float v0 = ((float)accM[mt][nt][0] + (float)accC[mt][nt][0] * INV254) * (sA0 * sB0);
            float v1 = ((float)accM[mt][nt][1] + (float)accC[mt][nt][1] * INV254) * (sA0 * sB1);
            float v2 = ((float)accM[mt][nt][2] + (float)accC[mt][nt][2] * INV254) * (sA8 * sB0);
            float v3 = ((float)accM[mt][nt][3] + (float)accC[mt][nt][3] * INV254) * (sA8 * sB1);
            if (op >= 1) {
                float b0 = bias[col], b1v = bias[col + 1];
                v0 += b0; v1 += b1v; v2 += b0; v3 += b1v;
            }
            if (op == 2) {
                v0 = fmaxf(v0, 0.f); v1 = fmaxf(v1, 0.f);
                v2 = fmaxf(v2, 0.f); v3 = fmaxf(v3, 0.f);
            }
            *(float2*)(C + (size_t)row * N + col) = make_float2(v0, v1);
            *(float2*)(C + (size_t)(row + 8) * N + col) = make_float2(v2, v3);
        }
    }
}

// ---------------------------------------------------------------------------
// fp32 GEMM (only for the 128x128 normal-equations matrix)
// ---------------------------------------------------------------------------
__global__ void __launch_bounds__(256) gemm_f32_kernel(
    const float* __restrict__ A, const float* __restrict__ B,
    float* __restrict__ C, int M, int N, int K)
{
    __shared__ float As[32][132];
    __shared__ float Bs[32][132];

    const int bm = blockIdx.y * 128;
    const int bn = blockIdx.x * 128;
    const int tid = threadIdx.x;
    const int tm = (tid >> 4) << 3;
    const int tn = (tid & 15) << 3;

    float acc[8][8];
#pragma unroll
    for (int i = 0; i < 8; i++)
#pragma unroll
        for (int j = 0; j < 8; j++) acc[i][j] = 0.f;

    for (int k0 = 0; k0 < K; k0 += 32) {
#pragma unroll
        for (int i = 0; i < 4; i++) {
            int idx = tid + i * 256;
            int row = idx >> 3;
            int col = (idx & 7) << 2;
            float4 a = *(const float4*)(A + (size_t)(bm + row) * K + k0 + col);
            As[col + 0][row] = a.x; As[col + 1][row] = a.y;
            As[col + 2][row] = a.z; As[col + 3][row] = a.w;
            float4 b = *(const float4*)(B + (size_t)(bn + row) * K + k0 + col);
            Bs[col + 0][row] = b.x; Bs[col + 1][row] = b.y;
            Bs[col + 2][row] = b.z; Bs[col + 3][row] = b.w;
        }
        __syncthreads();
#pragma unroll
        for (int kk = 0; kk < 32; kk++) {
            float av[8], bv[8];
#pragma unroll
            for (int i = 0; i < 8; i++) { av[i] = As[kk][tm + i]; bv[i] = Bs[kk][tn + i]; }
#pragma unroll
            for (int i = 0; i < 8; i++)
#pragma unroll
                for (int j = 0; j < 8; j++)
                    acc[i][j] += av[i] * bv[j];
        }
        __syncthreads();
    }
#pragma unroll
    for (int i = 0; i < 8; i++)
#pragma unroll
        for (int j = 0; j < 8; j++)
            C[(size_t)(bm + tm + i) * N + bn + tn + j] = acc[i][j];
}

// ---------------------------------------------------------------------------
// Gauss-Jordan inverse of SPD 128x128 g_M -> right half of g_aug
// ---------------------------------------------------------------------------
__global__ void __launch_bounds__(256) gj_kernel()
{
    const int tid = threadIdx.x;
    for (int idx = tid; idx < ODIM * 2 * ODIM; idx += 256) {
        int r = idx >> 8, c = idx & 255;
        g_aug[idx] = (c < ODIM) ? g_M[r * ODIM + c] : ((c - ODIM) == r ? 1.f : 0.f);
    }
    __syncthreads();

    const int r = tid >> 1;
    const int cb = (tid & 1) << 7;
    for (int k = 0; k < ODIM; k++) {
        float ip = 1.f / g_aug[k * 256 + k];
        __syncthreads();
        g_aug[k * 256 + tid] *= ip;
        __syncthreads();
        float f = (r != k) ? g_aug[r * 256 + k] : 0.f;
        __syncthreads();
        const float* prow = &g_aug[k * 256 + cb];
        float* rrow = &g_aug[r * 256 + cb];
#pragma unroll 8
        for (int c = 0; c < 128; c++) rrow[c] -= f * prow[c];
        __syncthreads();
    }
}

// P[o][e] = sum_j Minv[o][j] * W_obs[j][e]
__global__ void __launch_bounds__(256) pmat_kernel(const float* __restrict__ W)
{
    const int o = blockIdx.y;
    const int e = blockIdx.x * 256 + threadIdx.x;
    __shared__ float smv[ODIM];
    if (threadIdx.x < ODIM) smv[threadIdx.x] = g_aug[o * 256 + ODIM + threadIdx.x];
    __syncthreads();
    float acc = 0.f;
#pragma unroll 8
    for (int j = 0; j < ODIM; j++) acc += smv[j] * W[(size_t)j * EMB + e];
    g_P[(size_t)o * EMB + e] = acc;
}

// z[t][e] = sum_o x[t][o]*P[o][e] + PE(s,e); writes fp32 z + quantized row
__global__ void __launch_bounds__(256) embed_kernel(const float* __restrict__ x)
{
    __shared__ float sx[ODIM];
    __shared__ float sbuf[8];
    const int t = blockIdx.x;
    const int s = t & (SEQ - 1);
    if (threadIdx.x < ODIM) sx[threadIdx.x] = x[(size_t)t * ODIM + threadIdx.x];
    __syncthreads();
    float acc[4] = {0.f, 0.f, 0.f, 0.f};
#pragma unroll 4
    for (int o = 0; o < ODIM; o++) {
        float xv = sx[o];
        const float* pr = g_P + (size_t)o * EMB + threadIdx.x;
#pragma unroll
        for (int c = 0; c < 4; c++) acc[c] += xv * pr[c * 256];
    }
    const float kln = 9.210340371976184f / 1024.0f;
    float v[4];
    float m = 0.f;
#pragma unroll
    for (int c = 0; c < 4; c++) {
        int e = threadIdx.x + c * 256;
        float freq = expf(-(float)(e & ~1) * kln);
        float arg = (float)s * freq;
        float pe = (e & 1) ? cosf(arg) : sinf(arg);
        v[c] = acc[c] + pe;
        g_z[(size_t)t * EMB + e] = v[c];
        m = fmaxf(m, fabsf(v[c]));
    }
#pragma unroll
    for (int o = 16; o; o >>= 1) m = fmaxf(m, __shfl_xor_sync(0xffffffffu, m, o));
    if ((threadIdx.x & 31) == 0) sbuf[threadIdx.x >> 5] = m;
    __syncthreads();
    float mx = sbuf[0];
#pragma unroll
    for (int i = 1; i < 8; i++) mx = fmaxf(mx, sbuf[i]);
    mx = fmaxf(mx, 1e-30f);
    if (threadIdx.x == 0) g_zs[t] = mx;
    const float inv = 127.f / mx;
#pragma unroll
    for (int c = 0; c < 4; c++) {
        int e = threadIdx.x + c * 256;
        float xq = v[c] * inv;
        float r1 = rintf(xq);
        float r2 = rintf((xq - r1) * 254.f);
        g_zq1[(size_t)t * EMB + e] = (int8_t)r1;
        g_zq2[(size_t)t * EMB + e] = (int8_t)r2;
    }
}

// ---------------------------------------------------------------------------
// Attention: 8 warps per block = 8 queries of one (b,h)  (fp32 in/out)
// ---------------------------------------------------------------------------
__global__ void __launch_bounds__(256) attn_kernel(const float* __restrict__ qkv,
                                                   float* __restrict__ out)
{
    const int w = threadIdx.x >> 5, lane = threadIdx.x & 31;
    const int bh = blockIdx.x >> 6;
    const int qg = blockIdx.x & 63;
    const int b = bh >> 4, h = bh & 15;
    const int s = qg * 8 + w;

    __shared__ float sq[8][64];
    __shared__ float sp[8][512];
    __shared__ float st[32][68];

    const float* base = qkv + (size_t)(b * SEQ) * E3 + h * (3 * HDIM);
    {
        const float* qp = base + (size_t)s * E3;
        sq[w][lane] = qp[lane];
        sq[w][lane + 32] = qp[lane + 32];
    }

    for (int u0 = 0; u0 < SEQ; u0 += 32) {
        __syncthreads();
#pragma unroll
        for (int i = 0; i < 2; i++) {
            int idx = threadIdx.x + i * 256;
            int r = idx >> 4, c4 = (idx & 15) << 2;
            float4 kk = *(const float4*)(base + (size_t)(u0 + r) * E3 + HDIM + c4);
            *(float4*)(&st[r][c4]) = kk;
        }
        __syncthreads();
        float dot = 0.f;
#pragma unroll
        for (int d = 0; d < 64; d += 4) {
            float4 kk = *(const float4*)(&st[lane][d]);
            dot += kk.x * sq[w][d] + kk.y * sq[w][d + 1]
                 + kk.z * sq[w][d + 2] + kk.w * sq[w][d + 3];
        }
        sp[w][u0 + lane] = dot * 0.125f;
    }
    __syncthreads();

    float mx = -1e30f;
#pragma unroll
    for (int i = 0; i < 16; i++) mx = fmaxf(mx, sp[w][lane + i * 32]);
#pragma unroll
    for (int o = 16; o; o >>= 1) mx = fmaxf(mx, __shfl_xor_sync(0xffffffffu, mx, o));
    float sum = 0.f;
#pragma unroll
    for (int i = 0; i < 16; i++) {
        float p = __expf(sp[w][lane + i * 32] - mx);
        sp[w][lane + i * 32] = p;
        sum += p;
    }
#pragma unroll
    for (int o = 16; o; o >>= 1) sum += __shfl_xor_sync(0xffffffffu, sum, o);
    const float inv = 1.f / sum;

    float a0 = 0.f, a1 = 0.f;
    for (int u0 = 0; u0 < SEQ; u0 += 32) {
        __syncthreads();
#pragma unroll
        for (int i = 0; i < 2; i++) {
            int idx = threadIdx.x + i * 256;
            int r = idx >> 4, c4 = (idx & 15) << 2;
            float4 vv = *(const float4*)(base + (size_t)(u0 + r) * E3 + 2 * HDIM + c4);
            *(float4*)(&st[r][c4]) = vv;
        }
        __syncthreads();
#pragma unroll 8
        for (int u = 0; u < 32; u++) {
            float p = sp[w][u0 + u];
            float2 vv = *(const float2*)&st[u][2 * lane];
            a0 += p * vv.x;
            a1 += p * vv.y;
        }
    }
    const int t = b * SEQ + s;
    float* op = out + (size_t)t * EMB + h * HDIM + 2 * lane;
    op[0] = a0 * inv;
    op[1] = a1 * inv;
}

// ---------------------------------------------------------------------------
// Fused residual + LayerNorm; writes fp32 z + quantized row
// ---------------------------------------------------------------------------
__device__ __forceinline__ float block_sum256(float v, float* sbuf)
{
#pragma unroll
    for (int o = 16; o; o >>= 1) v += __shfl_xor_sync(0xffffffffu, v, o);
    if ((threadIdx.x & 31) == 0) sbuf[threadIdx.x >> 5] = v;
    __syncthreads();
    float tot = 0.f;
#pragma unroll
    for (int i = 0; i < 8; i++) tot += sbuf[i];
    return tot;
}

__global__ void __launch_bounds__(256) ln_kernel(float* __restrict__ z,
                                                 const float* __restrict__ add,
                                                 const float* __restrict__ g,
                                                 const float* __restrict__ b)
{
    __shared__ float red[24];
    const size_t t = blockIdx.x;
    float* zp = z + t * EMB;
    const float* ap = add + t * EMB;

    float v[4];
    float s = 0.f;
#pragma unroll
    for (int i = 0; i < 4; i++) {
        int e = threadIdx.x + i * 256;
        v[i] = zp[e] + ap[e];
        s += v[i];
    }
    float mean = block_sum256(s, red) * (1.f / 1024.f);
    float q = 0.f;
#pragma unroll
    for (int i = 0; i < 4; i++) { float d = v[i] - mean; q += d * d; }
    float var = block_sum256(q, red + 8) * (1.f / 1024.f);
    float rstd = rsqrtf(var + 1e-5f);

    float o[4];
    float m = 0.f;
#pragma unroll
    for (int i = 0; i < 4; i++) {
        int e = threadIdx.x + i * 256;
        o[i] = (v[i] - mean) * rstd * g[e] + b[e];
        zp[e] = o[i];
        m = fmaxf(m, fabsf(o[i]));
    }
#pragma unroll
    for (int ofs = 16; ofs; ofs >>= 1) m = fmaxf(m, __shfl_xor_sync(0xffffffffu, m, ofs));
    if ((threadIdx.x & 31) == 0) red[16 + (threadIdx.x >> 5)] = m;
    __syncthreads();
    float mx = red[16];
#pragma unroll
    for (int i = 1; i < 8; i++) mx = fmaxf(mx, red[16 + i]);
    mx = fmaxf(mx, 1e-30f);
    if (threadIdx.x == 0) g_zs[t] = mx;
    const float inv = 127.f / mx;
#pragma unroll
    for (int i = 0; i < 4; i++) {
        int e = threadIdx.x + i * 256;
        float xq = o[i] * inv;
        float r1 = rintf(xq);
        float r2 = rintf((xq - r1) * 254.f);
        g_zq1[t * EMB + e] = (int8_t)r1;
        g_zq2[t * EMB + e] = (int8_t)r2;
    }
}

// ---------------------------------------------------------------------------
// Launch
// ---------------------------------------------------------------------------
extern "C" void kernel_launch(void* const* d_in, const int* in_sizes, int n_in,
                              void* d_out, int out_size)
{
    const float* x     = (const float*)d_in[0];
    const float* W_obs = (const float*)d_in[1];
    const float* Wqkv  = (const float*)d_in[2];
    const float* Wo    = (const float*)d_in[3];
    const float* bo    = (const float*)d_in[4];
    const float* ln1g  = (const float*)d_in[5];
    const float* ln1b  = (const float*)d_in[6];
    const float* W1    = (const float*)d_in[7];
    const float* b1    = (const float*)d_in[8];
    const float* W2    = (const float*)d_in[9];
    const float* b2    = (const float*)d_in[10];
    const float* ln2g  = (const float*)d_in[11];
    const float* ln2b  = (const float*)d_in[12];
    float* out = (float*)d_out;

    float *z, *qkvb, *attnb, *tmpb, *hidb, *Mb, *ws, *zs, *as, *hs;
    int8_t *wq1, *wq2, *zq1, *zq2, *aq1, *aq2, *hq1, *hq2;
    cudaGetSymbolAddress((void**)&z,     g_z);
    cudaGetSymbolAddress((void**)&qkvb,  g_qkv);
    cudaGetSymbolAddress((void**)&attnb, g_attn);
    cudaGetSymbolAddress((void**)&tmpb,  g_tmp);
    cudaGetSymbolAddress((void**)&hidb,  g_hid);
    cudaGetSymbolAddress((void**)&Mb,    g_M);
    cudaGetSymbolAddress((void**)&wq1,   g_wq1);
    cudaGetSymbolAddress((void**)&wq2,   g_wq2);
    cudaGetSymbolAddress((void**)&ws,    g_ws);
    cudaGetSymbolAddress((void**)&zq1,   g_zq1);
    cudaGetSymbolAddress((void**)&zq2,   g_zq2);
    cudaGetSymbolAddress((void**)&zs,    g_zs);
    cudaGetSymbolAddress((void**)&aq1,   g_aq1);
    cudaGetSymbolAddress((void**)&aq2,   g_aq2);
    cudaGetSymbolAddress((void**)&as,    g_as);
    cudaGetSymbolAddress((void**)&hq1,   g_hq1);
    cudaGetSymbolAddress((void**)&hq2,   g_hq2);
    cudaGetSymbolAddress((void**)&hs,    g_hs);

    cudaFuncSetAttribute(gemm_i8_kernel,
                         cudaFuncAttributeMaxDynamicSharedMemorySize, TC_SMEM);

    // element offsets into limb arrays
    const size_t OQKV = 0;
    const size_t OO   = OQKV + (size_t)NLAYER * E3 * EMB;
    const size_t OW1  = OO   + (size_t)NLAYER * EMB * EMB;
    const size_t OW2  = OW1  + (size_t)NLAYER * HID * EMB;
    const size_t OOBS = OW2  + (size_t)NLAYER * EMB * HID;
    // row offsets into scale array
    const int RQKV = 0;
    const int RO   = RQKV + NLAYER * E3;     // 24576
    const int RW1  = RO   + NLAYER * EMB;    // 32768
    const int RW2  = RW1  + NLAYER * HID;    // 65536
    const int ROBS = RW2  + NLAYER * EMB;    // 73728

    // --- weight quantization (runs each launch; ~110us HBM-bound) ---
    quant_kernel<<<NLAYER * E3, 256>>>(Wqkv, wq1 + OQKV, wq2 + OQKV, ws + RQKV, EMB);
    quant_kernel<<<NLAYER * EMB, 256>>>(Wo, wq1 + OO, wq2 + OO, ws + RO, EMB);
    quant_kernel<<<NLAYER * HID, 256>>>(W1, wq1 + OW1, wq2 + OW1, ws + RW1, EMB);
    quant_kernel<<<NLAYER * EMB, 256>>>(W2, wq1 + OW2, wq2 + OW2, ws + RW2, HID);
    quant_kernel<<<ODIM, 256>>>(W_obs, wq1 + OOBS, wq2 + OOBS, ws + ROBS, EMB);

    // --- embed: pinv via normal equations (fp32 for conditioning) ---
    gemm_f32_kernel<<<dim3(1, 1), 256>>>(W_obs, W_obs, Mb, ODIM, ODIM, EMB);
    gj_kernel<<<1, 256>>>();
    pmat_kernel<<<dim3(EMB / 256, ODIM), 256>>>(W_obs);
    embed_kernel<<<NTOK, 256>>>(x);

    for (int l = 0; l < NLAYER; l++) {
        const size_t oq = OQKV + (size_t)l * E3 * EMB;
        const size_t oo = OO   + (size_t)l * EMB * EMB;
        const size_t o1 = OW1  + (size_t)l * HID * EMB;
        const size_t o2 = OW2  + (size_t)l * EMB * HID;

        gemm_i8_kernel<<<dim3(E3 / 128, NTOK / 128), 256, TC_SMEM>>>(
            zq1, zq2, zs, wq1 + oq, wq2 + oq, ws + RQKV + l * E3,
            nullptr, qkvb, NTOK, E3, EMB, 0);
        attn_kernel<<<BATCH * NHEAD * (SEQ / 8), 256>>>(qkvb, attnb);
        quant_kernel<<<NTOK, 256>>>(attnb, aq1, aq2, as, EMB);
        gemm_i8_kernel<<<dim3(EMB / 128, NTOK / 128), 256, TC_SMEM>>>(
            aq1, aq2, as, wq1 + oo, wq2 + oo, ws + RO + l * EMB,
            bo + l * EMB, tmpb, NTOK, EMB, EMB, 1);
        ln_kernel<<<NTOK, 256>>>(z, tmpb, ln1g + l * EMB, ln1b + l * EMB);
        gemm_i8_kernel<<<dim3(HID / 128, NTOK / 128), 256, TC_SMEM>>>(
            zq1, zq2, zs, wq1 + o1, wq2 + o1, ws + RW1 + l * HID,
            b1 + l * HID, hidb, NTOK, HID, EMB, 2);
        quant_kernel<<<NTOK, 256>>>(hidb, hq1, hq2, hs, HID);
        gemm_i8_kernel<<<dim3(EMB / 128, NTOK / 128), 256, TC_SMEM>>>(
            hq1, hq2, hs, wq1 + o2, wq2 + o2, ws + RW2 + l * EMB,
            b2 + l * EMB, tmpb, NTOK, EMB, HID, 1);
        ln_kernel<<<NTOK, 256>>>(z, tmpb, ln2g + l * EMB, ln2b + l * EMB);
    }

    // --- readout: x_hat = z @ W_obs^T ---
    gemm_i8_kernel<<<dim3(ODIM / 128, NTOK / 128), 256, TC_SMEM>>>(
        zq1, zq2, zs, wq1 + OOBS, wq2 + OOBS, ws + ROBS,
        nullptr, out, NTOK, ODIM, EMB, 0);
}

// round 14
// speedup vs baseline: 2.2163x; 2.2163x over previous
#include <cuda_runtime.h>
#include <cuda_bf16.h>
#include <cstdint>
#include <cstddef>

// Problem constants
#define BATCH 8
#define SEQ   512
#define NTOK  4096      // BATCH*SEQ
#define EMB   1024
#define E3    3072
#define NHEAD 16
#define HDIM  64
#define HID   4096
#define ODIM  128
#define NLAYER 8

// ---------------------------------------------------------------------------
// Scratch (device globals; allocation is forbidden)
// ---------------------------------------------------------------------------
__device__ float g_z   [(size_t)NTOK * EMB];   // 16 MB
__device__ float g_qkv [(size_t)NTOK * E3];    // 48 MB
__device__ float g_attn[(size_t)NTOK * EMB];   // 16 MB
__device__ float g_tmp [(size_t)NTOK * EMB];   // 16 MB
__device__ float g_hid [(size_t)NTOK * HID];   // 64 MB
__device__ float g_M   [ODIM * ODIM];
__device__ float g_aug [ODIM * 2 * ODIM];
__device__ float g_P   [ODIM * EMB];

// ---------------------------------------------------------------------------
// helpers
// ---------------------------------------------------------------------------
__device__ __forceinline__ void ldmatrix4(uint32_t addr, uint32_t& r0, uint32_t& r1,
                                          uint32_t& r2, uint32_t& r3)
{
    asm volatile("ldmatrix.sync.aligned.m8n8.x4.shared.b16 {%0,%1,%2,%3}, [%4];"
                 : "=r"(r0), "=r"(r1), "=r"(r2), "=r"(r3) : "r"(addr));
}

__device__ __forceinline__ void mma16816(float* c, uint32_t a0, uint32_t a1,
                                         uint32_t a2, uint32_t a3,
                                         uint32_t b0, uint32_t b1)
{
    asm volatile("mma.sync.aligned.m16n8k16.row.col.f32.bf16.bf16.f32 "
                 "{%0,%1,%2,%3},{%4,%5,%6,%7},{%8,%9},{%0,%1,%2,%3};"
                 : "+f"(c[0]), "+f"(c[1]), "+f"(c[2]), "+f"(c[3])
                 : "r"(a0), "r"(a1), "r"(a2), "r"(a3), "r"(b0), "r"(b1));
}

__device__ __forceinline__ void split2(float x, float y, uint32_t& h, uint32_t& l)
{
    __nv_bfloat162 hv = __floats2bfloat162_rn(x, y);
    float rx = x - __bfloat162float(hv.x);
    float ry = y - __bfloat162float(hv.y);
    __nv_bfloat162 lv = __floats2bfloat162_rn(rx, ry);
    h = *reinterpret_cast<uint32_t*>(&hv);
    l = *reinterpret_cast<uint32_t*>(&lv);
}

// ===========================================================================
// Tensor-core GEMM (round-2 champion, verbatim): C = A[M,K]*B[N,K]^T
// split-bf16, 3 HMMA terms, in-kernel convert (hidden under MMA issue shadow)
// ===========================================================================
#define TBM 128
#define TBN 128
#define TBK 32
#define RW  20
#define PLANE (128 * RW)
#define BUFW  (4 * PLANE)
#define TC_SMEM (2 * BUFW * 4)

__global__ void __launch_bounds__(256, 1) gemm_tc_kernel(
    const float* __restrict__ A, const float* __restrict__ B,
    const float* __restrict__ bias, float* __restrict__ C,
    int M, int N, int K, int op)   // op: 0=none, 1=bias, 2=bias+relu
{
    extern __shared__ uint32_t sm[];
    const uint32_t sbase = (uint32_t)__cvta_generic_to_shared(sm);

    const int tid = threadIdx.x;
    const int lane = tid & 31;
    const int wid = tid >> 5;
    const int wm = wid >> 2;
    const int wn = wid & 3;
    const int bm = blockIdx.y * TBM;
    const int bn = blockIdx.x * TBN;

    float acc[4][4][4];
#pragma unroll
    for (int i = 0; i < 4; i++)
#pragma unroll
        for (int j = 0; j < 4; j++)
#pragma unroll
            for (int r = 0; r < 4; r++) acc[i][j][r] = 0.f;

    int rows[4], c4s[4];
#pragma unroll
    for (int i = 0; i < 4; i++) {
        int f = tid + i * 256;
        rows[i] = f >> 3;
        c4s[i] = (f & 7) << 2;
    }

    const float* Ab = A + (size_t)bm * K;
    const float* Bb = B + (size_t)bn * K;

    float4 ra[4], rb[4];

#pragma unroll
    for (int i = 0; i < 4; i++) {
        ra[i] = *(const float4*)(Ab + (size_t)rows[i] * K + c4s[i]);
        rb[i] = *(const float4*)(Bb + (size_t)rows[i] * K + c4s[i]);
    }
    {
        uint32_t* buf = sm;
#pragma unroll
        for (int i = 0; i < 4; i++) {
            uint32_t h0, h1, l0, l1;
            int off = rows[i] * RW + (c4s[i] >> 1);
            split2(ra[i].x, ra[i].y, h0, l0);
            split2(ra[i].z, ra[i].w, h1, l1);
            buf[0 * PLANE + off] = h0; buf[0 * PLANE + off + 1] = h1;
            buf[1 * PLANE + off] = l0; buf[1 * PLANE + off + 1] = l1;
            split2(rb[i].x, rb[i].y, h0, l0);
            split2(rb[i].z, rb[i].w, h1, l1);
            buf[2 * PLANE + off] = h0; buf[2 * PLANE + off + 1] = h1;
            buf[3 * PLANE + off] = l0; buf[3 * PLANE + off + 1] = l1;
        }
    }
    __syncthreads();

    const int arow = wm * 64 + (lane & 7) + ((lane & 8) ? 8 : 0);
    const int akw0 = (lane & 16) ? 4 : 0;
    const int brow = wn * 32 + (lane & 7) + ((lane & 16) ? 8 : 0);
    const int bkw0 = (lane & 8) ? 4 : 0;

    const int T = K / TBK;
    for (int t = 0; t < T; t++) {
        if (t + 1 < T) {
            const int k0 = (t + 1) * TBK;
#pragma unroll
            for (int i = 0; i < 4; i++) {
                ra[i] = *(const float4*)(Ab + (size_t)rows[i] * K + k0 + c4s[i]);
                rb[i] = *(const float4*)(Bb + (size_t)rows[i] * K + k0 + c4s[i]);
            }
        }

        const uint32_t bufb = sbase + (uint32_t)((t & 1) * BUFW) * 4u;
#pragma unroll
        for (int ks = 0; ks < 2; ks++) {
            uint32_t ah[4][4], al[4][4], bh[4][2], bl[4][2];
            const int akw = ks * 8 + akw0;
            const int bkw = ks * 8 + bkw0;
#pragma unroll
            for (int mt = 0; mt < 4; mt++) {
                ldmatrix4(bufb + 4u * (0 * PLANE + (arow + mt * 16) * RW + akw),
                          ah[mt][0], ah[mt][1], ah[mt][2], ah[mt][3]);
                ldmatrix4(bufb + 4u * (1 * PLANE + (arow + mt * 16) * RW + akw),
                          al[mt][0], al[mt][1], al[mt][2], al[mt][3]);
            }
#pragma unroll
            for (int np = 0; np < 2; np++) {
                uint32_t r0, r1, r2, r3;
                ldmatrix4(bufb + 4u * (2 * PLANE + (brow + np * 16) * RW + bkw),
                          r0, r1, r2, r3);
                bh[2 * np][0] = r0; bh[2 * np][1] = r1;
                bh[2 * np + 1][0] = r2; bh[2 * np + 1][1] = r3;
                ldmatrix4(bufb + 4u * (3 * PLANE + (brow + np * 16) * RW + bkw),
                          r0, r1, r2, r3);
                bl[2 * np][0] = r0; bl[2 * np][1] = r1;
                bl[2 * np + 1][0] = r2; bl[2 * np + 1][1] = r3;
            }
#pragma unroll
            for (int mt = 0; mt < 4; mt++)
#pragma unroll
                for (int nt = 0; nt < 4; nt++) {
                    float* c = acc[mt][nt];
                    mma16816(c, ah[mt][0], ah[mt][1], ah[mt][2], ah[mt][3],
                             bh[nt][0], bh[nt][1]);
                    mma16816(c, ah[mt][0], ah[mt][1], ah[mt][2], ah[mt][3],
                             bl[nt][0], bl[nt][1]);
                    mma16816(c, al[mt][0], al[mt][1], al[mt][2], al[mt][3],
                             bh[nt][0], bh[nt][1]);
                }
        }
        __syncthreads();

        if (t + 1 < T) {
            uint32_t* buf = sm + ((t + 1) & 1) * BUFW;
#pragma unroll
            for (int i = 0; i < 4; i++) {
                uint32_t h0, h1, l0, l1;
                int off = rows[i] * RW + (c4s[i] >> 1);
                split2(ra[i].x, ra[i].y, h0, l0);
                split2(ra[i].z, ra[i].w, h1, l1);
                buf[0 * PLANE + off] = h0; buf[0 * PLANE + off + 1] = h1;
                buf[1 * PLANE + off] = l0; buf[1 * PLANE + off + 1] = l1;
                split2(rb[i].x, rb[i].y, h0, l0);
                split2(rb[i].z, rb[i].w, h1, l1);
                buf[2 * PLANE + off] = h0; buf[2 * PLANE + off + 1] = h1;
                buf[3 * PLANE + off] = l0; buf[3 * PLANE + off + 1] = l1;
            }
        }
        __syncthreads();
    }

#pragma unroll
    for (int mt = 0; mt < 4; mt++) {
        const int row = bm + wm * 64 + mt * 16 + (lane >> 2);
#pragma unroll
        for (int nt = 0; nt < 4; nt++) {
            const int col = bn + wn * 32 + nt * 8 + 2 * (lane & 3);
            float b0 = 0.f, b1 = 0.f;
            if (op >= 1) { b0 = bias[col]; b1 = bias[col + 1]; }
            float v0 = acc[mt][nt][0] + b0;
            float v1 = acc[mt][nt][1] + b1;
            float v2 = acc[mt][nt][2] + b0;
            float v3 = acc[mt][nt][3] + b1;
            if (op == 2) {
                v0 = fmaxf(v0, 0.f); v1 = fmaxf(v1, 0.f);
                v2 = fmaxf(v2, 0.f); v3 = fmaxf(v3, 0.f);
            }
            *(float2*)(C + (size_t)row * N + col) = make_float2(v0, v1);
            *(float2*)(C + (size_t)(row + 8) * N + col) = make_float2(v2, v3);
        }
    }
}

// ===========================================================================
// Tensor-core flash attention: one (b,h) x 128-query tile per CTA.
// grid(4, B*H), 256 threads (8 warps as 2(wm) x 4(wn)).
// Scores and P*V via 3-term split-bf16 MMA; flash softmax in registers.
// ===========================================================================
#define RWQ 36                   // Q/K tile row stride (words): 32 data + 4 pad
#define RWP 68                   // P/V^T row stride (words): 64 data + 4 pad
#define AQH 0
#define AQL 4608
#define AKH 9216
#define AKL 13824
#define AVH 18432
#define AVL 22784
#define APH 27136
#define APL 35840
#define AWMAX 44544
#define AWSUM 45056
#define ATT_SMEM (45568 * 4)

__global__ void __launch_bounds__(256, 1) attn_mma_kernel(
    const float* __restrict__ qkv, float* __restrict__ out)
{
    extern __shared__ uint32_t sm[];
    const uint32_t sbase = (uint32_t)__cvta_generic_to_shared(sm);
    __nv_bfloat16* smh = (__nv_bfloat16*)sm;

    const int tid = threadIdx.x;
    const int lane = tid & 31;
    const int wid = tid >> 5;
    const int wm = wid >> 2, wn = wid & 3;
    const int qg = blockIdx.x;
    const int b = blockIdx.y >> 4, h = blockIdx.y & 15;

    const float* base = qkv + (size_t)(b * SEQ) * E3 + h * (3 * HDIM);

    // ---- stage Q (128 x 64, split bf16) ----
#pragma unroll
    for (int i = 0; i < 8; i++) {
        int f = tid + i * 256;
        int row = f >> 4, c4 = (f & 15) << 2;
        float4 v = *(const float4*)(base + (size_t)(qg * 128 + row) * E3 + c4);
        uint32_t h0, l0, h1, l1;
        split2(v.x, v.y, h0, l0);
        split2(v.z, v.w, h1, l1);
        int off = row * RWQ + (c4 >> 1);
        sm[AQH + off] = h0; sm[AQH + off + 1] = h1;
        sm[AQL + off] = l0; sm[AQL + off + 1] = l1;
    }

    float accO[4][2][4];
    float m_reg[4][2], l_reg[4][2];
#pragma unroll
    for (int mt = 0; mt < 4; mt++) {
#pragma unroll
        for (int n2 = 0; n2 < 2; n2++)
#pragma unroll
            for (int r = 0; r < 4; r++) accO[mt][n2][r] = 0.f;
        m_reg[mt][0] = -1e30f; m_reg[mt][1] = -1e30f;
        l_reg[mt][0] = 0.f;    l_reg[mt][1] = 0.f;
    }

    const int arow = wm * 64 + (lane & 7) + ((lane & 8) ? 8 : 0);
    const int akw0 = (lane & 16) ? 4 : 0;
    const int brow = wn * 32 + (lane & 7) + ((lane & 16) ? 8 : 0);
    const int bkw0 = (lane & 8) ? 4 : 0;
    const int brow2 = wn * 16 + (lane & 7) + ((lane & 16) ? 8 : 0);
    const int rbase0 = wm * 64 + (lane >> 2);

    float* wmaxf = (float*)&sm[AWMAX];
    float* wsumf = (float*)&sm[AWSUM];

    for (int c = 0; c < 4; c++) {
        __syncthreads();   // prior chunk's ldmatrix reads done before restaging

        // ---- stage K chunk (128 x 64, split) ----
#pragma unroll
        for (int i = 0; i < 8; i++) {
            int f = tid + i * 256;
            int row = f >> 4, c4 = (f & 15) << 2;
            float4 v = *(const float4*)(base + (size_t)(c * 128 + row) * E3 + HDIM + c4);
            uint32_t h0, l0, h1, l1;
            split2(v.x, v.y, h0, l0);
            split2(v.z, v.w, h1, l1);
            int off = row * RWQ + (c4 >> 1);
            sm[AKH + off] = h0; sm[AKH + off + 1] = h1;
            sm[AKL + off] = l0; sm[AKL + off + 1] = l1;
        }
        // ---- stage V^T chunk (64 x 128, split, transposed scalar stores) ----
#pragma unroll
        for (int i = 0; i < 8; i++) {
            int f = tid + i * 256;
            int r = f >> 4, d4 = (f & 15) << 2;
            float4 v = *(const float4*)(base + (size_t)(c * 128 + r) * E3 + 2 * HDIM + d4);
            float vv[4] = {v.x, v.y, v.z, v.w};
#pragma unroll
            for (int j = 0; j < 4; j++) {
                __nv_bfloat16 hb = __float2bfloat16_rn(vv[j]);
                __nv_bfloat16 lb = __float2bfloat16_rn(vv[j] - __bfloat162float(hb));
                smh[(AVH + (d4 + j) * RWP) * 2 + r] = hb;
                smh[(AVL + (d4 + j) * RWP) * 2 + r] = lb;
            }
        }
        __syncthreads();

        // ---- scores: S = Q K^T (3-term split) ----
        float accS[4][4][4];
#pragma unroll
        for (int i = 0; i < 4; i++)
#pragma unroll
            for (int j = 0; j < 4; j++)
#pragma unroll
                for (int r = 0; r < 4; r++) accS[i][j][r] = 0.f;

#pragma unroll
        for (int kt = 0; kt < 2; kt++)
#pragma unroll
            for (int ks = 0; ks < 2; ks++) {
                const int akw = kt * 16 + ks * 8 + akw0;
                const int bkw = kt * 16 + ks * 8 + bkw0;
                uint32_t qh[4][4], ql[4][4], kh[4][2], kl[4][2];
#pragma unroll
                for (int mt = 0; mt < 4; mt++) {
                    ldmatrix4(sbase + 4u * (AQH + (arow + mt * 16) * RWQ + akw),
                              qh[mt][0], qh[mt][1], qh[mt][2], qh[mt][3]);
                    ldmatrix4(sbase + 4u * (AQL + (arow + mt * 16) * RWQ + akw),
                              ql[mt][0], ql[mt][1], ql[mt][2], ql[mt][3]);
                }
#pragma unroll
                for (int np = 0; np < 2; np++) {
                    uint32_t r0, r1, r2, r3;
                    ldmatrix4(sbase + 4u * (AKH + (brow + np * 16) * RWQ + bkw),
                              r0, r1, r2, r3);
                    kh[2 * np][0] = r0; kh[2 * np][1] = r1;
                    kh[2 * np + 1][0] = r2; kh[2 * np + 1][1] = r3;
                    ldmatrix4(sbase + 4u * (AKL + (brow + np * 16) * RWQ + bkw),
                              r0, r1, r2, r3);
                    kl[2 * np][0] = r0; kl[2 * np][1] = r1;
                    kl[2 * np + 1][0] = r2; kl[2 * np + 1][1] = r3;
                }
#pragma unroll
                for (int mt = 0; mt < 4; mt++)
#pragma unroll
                    for (int nt = 0; nt < 4; nt++) {
                        float* cc = accS[mt][nt];
                        mma16816(cc, qh[mt][0], qh[mt][1], qh[mt][2], qh[mt][3],
                                 kh[nt][0], kh[nt][1]);
                        mma16816(cc, qh[mt][0], qh[mt][1], qh[mt][2], qh[mt][3],
                                 kl[nt][0], kl[nt][1]);
                        mma16816(cc, ql[mt][0], ql[mt][1], ql[mt][2], ql[mt][3],
                                 kh[nt][0], kh[nt][1]);
                    }
            }

        // ---- row max over this chunk (warp part) ----
#pragma unroll
        for (int mt = 0; mt < 4; mt++) {
            float x0 = accS[mt][0][0], x1 = accS[mt][0][2];
#pragma unroll
            for (int nt = 0; nt < 4; nt++) {
                x0 = fmaxf(x0, fmaxf(accS[mt][nt][0], accS[mt][nt][1]));
                x1 = fmaxf(x1, fmaxf(accS[mt][nt][2], accS[mt][nt][3]));
            }
            x0 = fmaxf(x0, __shfl_xor_sync(0xffffffffu, x0, 1));
            x0 = fmaxf(x0, __shfl_xor_sync(0xffffffffu, x0, 2));
            x1 = fmaxf(x1, __shfl_xor_sync(0xffffffffu, x1, 1));
            x1 = fmaxf(x1, __shfl_xor_sync(0xffffffffu, x1, 2));
            if ((lane & 3) == 0) {
                wmaxf[wn * 128 + rbase0 + mt * 16] = x0;
                wmaxf[wn * 128 + rbase0 + mt * 16 + 8] = x1;
            }
        }
        __syncthreads();

        // ---- flash update: new max, alpha, p, P write, partial sums ----
        float alpha[4][2], psum[4][2];
#pragma unroll
        for (int mt = 0; mt < 4; mt++)
#pragma unroll
            for (int j = 0; j < 2; j++) {
                int row = rbase0 + mt * 16 + j * 8;
                float mc = fmaxf(fmaxf(wmaxf[row], wmaxf[128 + row]),
                                 fmaxf(wmaxf[256 + row], wmaxf[384 + row])) * 0.125f;
                float mn = fmaxf(m_reg[mt][j], mc);
                alpha[mt][j] = __expf(m_reg[mt][j] - mn);
                m_reg[mt][j] = mn;
                psum[mt][j] = 0.f;
            }
#pragma unroll
        for (int mt = 0; mt < 4; mt++) {
            const int row = rbase0 + mt * 16;
#pragma unroll
            for (int nt = 0; nt < 4; nt++) {
                const int col = wn * 32 + nt * 8 + 2 * (lane & 3);
                float p0 = __expf(accS[mt][nt][0] * 0.125f - m_reg[mt][0]);
                float p1 = __expf(accS[mt][nt][1] * 0.125f - m_reg[mt][0]);
                float p2 = __expf(accS[mt][nt][2] * 0.125f - m_reg[mt][1]);
                float p3 = __expf(accS[mt][nt][3] * 0.125f - m_reg[mt][1]);
                psum[mt][0] += p0 + p1;
                psum[mt][1] += p2 + p3;
                uint32_t hh, ll;
                split2(p0, p1, hh, ll);
                sm[APH + row * RWP + (col >> 1)] = hh;
                sm[APL + row * RWP + (col >> 1)] = ll;
                split2(p2, p3, hh, ll);
                sm[APH + (row + 8) * RWP + (col >> 1)] = hh;
                sm[APL + (row + 8) * RWP + (col >> 1)] = ll;
            }
        }
#pragma unroll
        for (int mt = 0; mt < 4; mt++)
#pragma unroll
            for (int j = 0; j < 2; j++) {
                float s = psum[mt][j];
                s += __shfl_xor_sync(0xffffffffu, s, 1);
                s += __shfl_xor_sync(0xffffffffu, s, 2);
                psum[mt][j] = s;
            }
        if ((lane & 3) == 0)
#pragma unroll
            for (int mt = 0; mt < 4; mt++) {
                wsumf[wn * 128 + rbase0 + mt * 16] = psum[mt][0];
                wsumf[wn * 128 + rbase0 + mt * 16 + 8] = psum[mt][1];
            }
        // rescale running output
#pragma unroll
        for (int mt = 0; mt < 4; mt++)
#pragma unroll
            for (int n2 = 0; n2 < 2; n2++) {
                accO[mt][n2][0] *= alpha[mt][0];
                accO[mt][n2][1] *= alpha[mt][0];
                accO[mt][n2][2] *= alpha[mt][1];
                accO[mt][n2][3] *= alpha[mt][1];
            }
        __syncthreads();

        // ---- l update ----
#pragma unroll
        for (int mt = 0; mt < 4; mt++)
#pragma unroll
            for (int j = 0; j < 2; j++) {
                int row = rbase0 + mt * 16 + j * 8;
                float s = wsumf[row] + wsumf[128 + row] + wsumf[256 + row] + wsumf[384 + row];
                l_reg[mt][j] = l_reg[mt][j] * alpha[mt][j] + s;
            }

        // ---- AV: O += P V (3-term split) ----
#pragma unroll
        for (int kt = 0; kt < 4; kt++)
#pragma unroll
            for (int ks = 0; ks < 2; ks++) {
                const int akw = kt * 16 + ks * 8 + akw0;
                const int bkw = kt * 16 + ks * 8 + bkw0;
                uint32_t ph[4][4], pl[4][4], vh[2][2], vl[2][2];
#pragma unroll
                for (int mt = 0; mt < 4; mt++) {
                    ldmatrix4(sbase + 4u * (APH + (arow + mt * 16) * RWP + akw),
                              ph[mt][0], ph[mt][1], ph[mt][2], ph[mt][3]);
                    ldmatrix4(sbase + 4u * (APL + (arow + mt * 16) * RWP + akw),
                              pl[mt][0], pl[mt][1], pl[mt][2], pl[mt][3]);
                }
                {
                    uint32_t r0, r1, r2, r3;
                    ldmatrix4(sbase + 4u * (AVH + brow2 * RWP + bkw), r0, r1, r2, r3);
                    vh[0][0] = r0; vh[0][1] = r1; vh[1][0] = r2; vh[1][1] = r3;
                    ldmatrix4(sbase + 4u * (AVL + brow2 * RWP + bkw), r0, r1, r2, r3);
                    vl[0][0] = r0; vl[0][1] = r1; vl[1][0] = r2; vl[1][1] = r3;
                }
#pragma unroll
                for (int mt = 0; mt < 4; mt++)
#pragma unroll
                    for (int n2 = 0; n2 < 2; n2++) {
                        float* cc = accO[mt][n2];
                        mma16816(cc, ph[mt][0], ph[mt][1], ph[mt][2], ph[mt][3],
                                 vh[n2][0], vh[n2][1]);
                        mma16816(cc, ph[mt][0], ph[mt][1], ph[mt][2], ph[mt][3],
                                 vl[n2][0], vl[n2][1]);
                        mma16816(cc, pl[mt][0], pl[mt][1], pl[mt][2], pl[mt][3],
                                 vh[n2][0], vh[n2][1]);
                    }
            }
    }

    // ---- epilogue: divide by l and store ----
#pragma unroll
    for (int mt = 0; mt < 4; mt++) {
        const int row = rbase0 + mt * 16;
        const int t0 = b * SEQ + qg * 128 + row;
        const float inv0 = 1.f / l_reg[mt][0];
        const float inv1 = 1.f / l_reg[mt][1];
#pragma unroll
        for (int n2 = 0; n2 < 2; n2++) {
            const int col = wn * 16 + n2 * 8 + 2 * (lane & 3);
            *(float2*)(out + (size_t)t0 * EMB + h * HDIM + col) =
                make_float2(accO[mt][n2][0] * inv0, accO[mt][n2][1] * inv0);
            *(float2*)(out + (size_t)(t0 + 8) * EMB + h * HDIM + col) =
                make_float2(accO[mt][n2][2] * inv1, accO[mt][n2][3] * inv1);
        }
    }
}

// ---------------------------------------------------------------------------
// fp32 GEMM (only for the 128x128 normal-equations matrix)
// ---------------------------------------------------------------------------
__global__ void __launch_bounds__(256) gemm_f32_kernel(
    const float* __restrict__ A, const float* __restrict__ B,
    float* __restrict__ C, int M, int N, int K)
{
    __shared__ float As[32][132];
    __shared__ float Bs[32][132];

    const int bm = blockIdx.y * 128;
    const int bn = blockIdx.x * 128;
    const int tid = threadIdx.x;
    const int tm = (tid >> 4) << 3;
    const int tn = (tid & 15) << 3;

    float acc[8][8];
#pragma unroll
    for (int i = 0; i < 8; i++)
#pragma unroll
        for (int j = 0; j < 8; j++) acc[i][j] = 0.f;

    for (int k0 = 0; k0 < K; k0 += 32) {
#pragma unroll
        for (int i = 0; i < 4; i++) {
            int idx = tid + i * 256;
            int row = idx >> 3;
            int col = (idx & 7) << 2;
            float4 a = *(const float4*)(A + (size_t)(bm + row) * K + k0 + col);
            As[col + 0][row] = a.x; As[col + 1][row] = a.y;
            As[col + 2][row] = a.z; As[col + 3][row] = a.w;
            float4 b = *(const float4*)(B + (size_t)(bn + row) * K + k0 + col);
            Bs[col + 0][row] = b.x; Bs[col + 1][row] = b.y;
            Bs[col + 2][row] = b.z; Bs[col + 3][row] = b.w;
        }
        __syncthreads();
#pragma unroll
        for (int kk = 0; kk < 32; kk++) {
            float av[8], bv[8];
#pragma unroll
            for (int i = 0; i < 8; i++) { av[i] = As[kk][tm + i]; bv[i] = Bs[kk][tn + i]; }
#pragma unroll
            for (int i = 0; i < 8; i++)
#pragma unroll
                for (int j = 0; j < 8; j++)
                    acc[i][j] += av[i] * bv[j];
        }
        __syncthreads();
    }
#pragma unroll
    for (int i = 0; i < 8; i++)
#pragma unroll
        for (int j = 0; j < 8; j++)
            C[(size_t)(bm + tm + i) * N + bn + tn + j] = acc[i][j];
}

// ---------------------------------------------------------------------------
// Gauss-Jordan inverse of SPD 128x128 g_M -> right half of g_aug
// ---------------------------------------------------------------------------
__global__ void __launch_bounds__(256) gj_kernel()
{
    const int tid = threadIdx.x;
    for (int idx = tid; idx < ODIM * 2 * ODIM; idx += 256) {
        int r = idx >> 8, c = idx & 255;
        g_aug[idx] = (c < ODIM) ? g_M[r * ODIM + c] : ((c - ODIM) == r ? 1.f : 0.f);
    }
    __syncthreads();

    const int r = tid >> 1;
    const int cb = (tid & 1) << 7;
    for (int k = 0; k < ODIM; k++) {
        float ip = 1.f / g_aug[k * 256 + k];
        __syncthreads();
        g_aug[k * 256 + tid] *= ip;
        __syncthreads();
        float f = (r != k) ? g_aug[r * 256 + k] : 0.f;
        __syncthreads();
        const float* prow = &g_aug[k * 256 + cb];
        float* rrow = &g_aug[r * 256 + cb];
#pragma unroll 8
        for (int c = 0; c < 128; c++) rrow[c] -= f * prow[c];
        __syncthreads();
    }
}

// P[o][e] = sum_j Minv[o][j] * W_obs[j][e]
__global__ void __launch_bounds__(256) pmat_kernel(const float* __restrict__ W)
{
    const int o = blockIdx.y;
    const int e = blockIdx.x * 256 + threadIdx.x;
    __shared__ float smv[ODIM];
    if (threadIdx.x < ODIM) smv[threadIdx.x] = g_aug[o * 256 + ODIM + threadIdx.x];
    __syncthreads();
    float acc = 0.f;
#pragma unroll 8
    for (int j = 0; j < ODIM; j++) acc += smv[j] * W[(size_t)j * EMB + e];
    g_P[(size_t)o * EMB + e] = acc;
}

// z[t][e] = sum_o x[t][o] * P[o][e] + PE(s,e)
__global__ void __launch_bounds__(256) embed_kernel(const float* __restrict__ x)
{
    const int t = blockIdx.x;
    const int s = t & (SEQ - 1);
    __shared__ float sx[ODIM];
    if (threadIdx.x < ODIM) sx[threadIdx.x] = x[(size_t)t * ODIM + threadIdx.x];
    __syncthreads();
    float acc[4] = {0.f, 0.f, 0.f, 0.f};
#pragma unroll 4
    for (int o = 0; o < ODIM; o++) {
        float xv = sx[o];
        const float* pr = g_P + (size_t)o * EMB + threadIdx.x;
#pragma unroll
        for (int c = 0; c < 4; c++) acc[c] += xv * pr[c * 256];
    }
    const float kln = 9.210340371976184f / 1024.0f;
#pragma unroll
    for (int c = 0; c < 4; c++) {
        int e = threadIdx.x + c * 256;
        float freq = expf(-(float)(e & ~1) * kln);
        float arg = (float)s * freq;
        float pe = (e & 1) ? cosf(arg) : sinf(arg);
        g_z[(size_t)t * EMB + e] = acc[c] + pe;
    }
}

// ---------------------------------------------------------------------------
// Fused residual + LayerNorm (in place on z)
// ---------------------------------------------------------------------------
__device__ __forceinline__ float block_sum256(float v, float* sbuf)
{
#pragma unroll
    for (int o = 16; o; o >>= 1) v += __shfl_xor_sync(0xffffffffu, v, o);
    if ((threadIdx.x & 31) == 0) sbuf[threadIdx.x >> 5] = v;
    __syncthreads();
    float tot = 0.f;
#pragma unroll
    for (int i = 0; i < 8; i++) tot += sbuf[i];
    return tot;
}

__global__ void __launch_bounds__(256) ln_kernel(float* __restrict__ z,
                                                 const float* __restrict__ add,
                                                 const float* __restrict__ g,
                                                 const float* __restrict__ b)
{
    __shared__ float red[16];
    const size_t t = blockIdx.x;
    float* zp = z + t * EMB;
    const float* ap = add + t * EMB;

    float v[4];
    float s = 0.f;
#pragma unroll
    for (int i = 0; i < 4; i++) {
        int e = threadIdx.x + i * 256;
        v[i] = zp[e] + ap[e];
        s += v[i];
    }
    float mean = block_sum256(s, red) * (1.f / 1024.f);
    float q = 0.f;
#pragma unroll
    for (int i = 0; i < 4; i++) { float d = v[i] - mean; q += d * d; }
    float var = block_sum256(q, red + 8) * (1.f / 1024.f);
    float rstd = rsqrtf(var + 1e-5f);
#pragma unroll
    for (int i = 0; i < 4; i++) {
        int e = threadIdx.x + i * 256;
        zp[e] = (v[i] - mean) * rstd * g[e] + b[e];
    }
}

// ---------------------------------------------------------------------------
// Launch
// ---------------------------------------------------------------------------
extern "C" void kernel_launch(void* const* d_in, const int* in_sizes, int n_in,
                              void* d_out, int out_size)
{
    const float* x     = (const float*)d_in[0];
    const float* W_obs = (const float*)d_in[1];
    const float* Wqkv  = (const float*)d_in[2];
    const float* Wo    = (const float*)d_in[3];
    const float* bo    = (const float*)d_in[4];
    const float* ln1g  = (const float*)d_in[5];
    const float* ln1b  = (const float*)d_in[6];
    const float* W1    = (const float*)d_in[7];
    const float* b1    = (const float*)d_in[8];
    const float* W2    = (const float*)d_in[9];
    const float* b2    = (const float*)d_in[10];
    const float* ln2g  = (const float*)d_in[11];
    const float* ln2b  = (const float*)d_in[12];
    float* out = (float*)d_out;

    float *z, *qkvb, *attnb, *tmpb, *hidb, *Mb;
    cudaGetSymbolAddress((void**)&z,     g_z);
    cudaGetSymbolAddress((void**)&qkvb,  g_qkv);
    cudaGetSymbolAddress((void**)&attnb, g_attn);
    cudaGetSymbolAddress((void**)&tmpb,  g_tmp);
    cudaGetSymbolAddress((void**)&hidb,  g_hid);
    cudaGetSymbolAddress((void**)&Mb,    g_M);

    cudaFuncSetAttribute(gemm_tc_kernel,
                         cudaFuncAttributeMaxDynamicSharedMemorySize, TC_SMEM);
    cudaFuncSetAttribute(attn_mma_kernel,
                         cudaFuncAttributeMaxDynamicSharedMemorySize, ATT_SMEM);

    // --- embed: pinv via normal equations (fp32 for conditioning) ---
    gemm_f32_kernel<<<dim3(1, 1), 256>>>(W_obs, W_obs, Mb, ODIM, ODIM, EMB);
    gj_kernel<<<1, 256>>>();
    pmat_kernel<<<dim3(EMB / 256, ODIM), 256>>>(W_obs);
    embed_kernel<<<NTOK, 256>>>(x);

    for (int l = 0; l < NLAYER; l++) {
        const float* wqkv_l = Wqkv + (size_t)l * E3 * EMB;
        const float* wo_l   = Wo   + (size_t)l * EMB * EMB;
        const float* w1_l   = W1   + (size_t)l * HID * EMB;
        const float* w2_l   = W2   + (size_t)l * EMB * HID;

        gemm_tc_kernel<<<dim3(E3 / TBN, NTOK / TBM), 256, TC_SMEM>>>(
            z, wqkv_l, nullptr, qkvb, NTOK, E3, EMB, 0);
        attn_mma_kernel<<<dim3(SEQ / 128, BATCH * NHEAD), 256, ATT_SMEM>>>(qkvb, attnb);
        gemm_tc_kernel<<<dim3(EMB / TBN, NTOK / TBM), 256, TC_SMEM>>>(
            attnb, wo_l, bo + l * EMB, tmpb, NTOK, EMB, EMB, 1);
        ln_kernel<<<NTOK, 256>>>(z, tmpb, ln1g + l * EMB, ln1b + l * EMB);
        gemm_tc_kernel<<<dim3(HID / TBN, NTOK / TBM), 256, TC_SMEM>>>(
            z, w1_l, b1 + l * HID, hidb, NTOK, HID, EMB, 2);
        gemm_tc_kernel<<<dim3(EMB / TBN, NTOK / TBM), 256, TC_SMEM>>>(
            hidb, w2_l, b2 + l * EMB, tmpb, NTOK, EMB, HID, 1);
        ln_kernel<<<NTOK, 256>>>(z, tmpb, ln2g + l * EMB, ln2b + l * EMB);
    }

    // --- readout: x_hat = z @ W_obs^T ---
    gemm_tc_kernel<<<dim3(ODIM / TBN, NTOK / TBM), 256, TC_SMEM>>>(
        z, W_obs, nullptr, out, NTOK, ODIM, EMB, 0);
}